// round 2
// baseline (speedup 1.0000x reference)
#include <cuda_runtime.h>
#include <cuda_bf16.h>
#include <cfloat>
#include <cub/cub.cuh>

#define KC 16
#define DC 64
#define NMAX 131072
#define CHUNK 256
#define NCHUNK_MAX (NMAX / CHUNK)

// ---------------- static device scratch (no allocations allowed) ----------------
__device__ int   g_pred[NMAX];
__device__ int   g_ccx[NCHUNK_MAX * KC];   // per-chunk cluster counts (x)
__device__ int   g_cct[NCHUNK_MAX * KC];   // per-chunk cluster counts (t)
__device__ int   g_cbx[NCHUNK_MAX * KC];   // per-chunk exclusive bases (x)
__device__ int   g_cbt[NCHUNK_MAX * KC];   // per-chunk exclusive bases (t)
__device__ int   g_cntx[KC], g_cntt[KC], g_m[KC], g_off[KC], g_pow[KC];
__device__ float g_fill[KC];
__device__ float g_loss;
// segment layout: cluster k occupies rows [g_off[k], g_off[k]+g_pow[k]) of a
// conceptual [2N, D] buffer; dim d of cluster k is contiguous at
// base = g_off[k]*DC + d*g_pow[k], valid length g_m[k], padding up to g_pow[k].
__device__ float g_bufx[2u * NMAX * DC];
__device__ float g_buft[2u * NMAX * DC];

// ---------------- init ----------------
__global__ void initK() {
    int t = threadIdx.x;
    if (t < KC) g_fill[t] = 0.f;
    if (t == 0) g_loss = 0.f;
}

// ---------------- assignment + softmax filling + per-chunk counts ----------------
__global__ void assignK(const float* __restrict__ x, const float* __restrict__ C, int N) {
    __shared__ float4 sC[KC * DC / 4];   // 256 float4 = centers [16,64]
    __shared__ float  sCC[KC];
    __shared__ float  sFill[KC];
    __shared__ int    sCnt[KC];
    int tid = threadIdx.x;
    sC[tid] = ((const float4*)C)[tid];
    if (tid < KC) { sFill[tid] = 0.f; sCnt[tid] = 0; }
    __syncthreads();
    if (tid < KC) {
        float cc = 0.f;
        #pragma unroll
        for (int q = 0; q < DC / 4; q++) {
            float4 c = sC[tid * (DC / 4) + q];
            cc += c.x * c.x + c.y * c.y + c.z * c.z + c.w * c.w;
        }
        sCC[tid] = cc;
    }
    __syncthreads();

    int i = blockIdx.x * blockDim.x + tid;
    bool act = i < N;
    float sc[KC];
    int bk = 0;
    if (act) {
        float acc[KC];
        #pragma unroll
        for (int k = 0; k < KC; k++) acc[k] = 0.f;
        const float4* xr = (const float4*)(x + (size_t)i * DC);
        #pragma unroll
        for (int q = 0; q < DC / 4; q++) {
            float4 v = xr[q];
            #pragma unroll
            for (int k = 0; k < KC; k++) {
                float4 c = sC[k * (DC / 4) + q];
                acc[k] += v.x * c.x + v.y * c.y + v.z * c.z + v.w * c.w;
            }
        }
        float best = FLT_MAX;
        #pragma unroll
        for (int k = 0; k < KC; k++) {
            sc[k] = sCC[k] - 2.f * acc[k];   // ||x||^2 cancels in argmin & softmax
            if (sc[k] < best) { best = sc[k]; bk = k; }
        }
        g_pred[i] = bk;
        float sum = 0.f;
        #pragma unroll
        for (int k = 0; k < KC; k++) { float e = __expf(-4.f * (sc[k] - best)); sc[k] = e; sum += e; }
        float inv = 1.f / sum;
        #pragma unroll
        for (int k = 0; k < KC; k++) sc[k] *= inv;
        atomicAdd(&sCnt[bk], 1);
    } else {
        #pragma unroll
        for (int k = 0; k < KC; k++) sc[k] = 0.f;
    }
    int lane = tid & 31;
    #pragma unroll
    for (int k = 0; k < KC; k++) {
        float v = sc[k];
        v += __shfl_down_sync(0xffffffffu, v, 16);
        v += __shfl_down_sync(0xffffffffu, v, 8);
        v += __shfl_down_sync(0xffffffffu, v, 4);
        v += __shfl_down_sync(0xffffffffu, v, 2);
        v += __shfl_down_sync(0xffffffffu, v, 1);
        if (lane == 0) atomicAdd(&sFill[k], v);
    }
    __syncthreads();
    if (tid < KC) {
        g_ccx[blockIdx.x * KC + tid] = sCnt[tid];
        atomicAdd(&g_fill[tid], sFill[tid]);
    }
}

// ---------------- per-chunk counts for target's prediction ----------------
__global__ void countTK(const int* __restrict__ pr, int N) {
    __shared__ int sCnt[KC];
    int tid = threadIdx.x;
    if (tid < KC) sCnt[tid] = 0;
    __syncthreads();
    int i = blockIdx.x * blockDim.x + tid;
    if (i < N) atomicAdd(&sCnt[pr[i]], 1);
    __syncthreads();
    if (tid < KC) g_cct[blockIdx.x * KC + tid] = sCnt[tid];
}

// ---------------- scan: chunk bases, totals, m, pow2 pad, segment offsets ----------------
__global__ void scanK(int nchunk) {
    int t = threadIdx.x;
    if (t < 32) {
        int k = t & 15;
        const int* cc = (t < 16) ? g_ccx : g_cct;
        int* cb       = (t < 16) ? g_cbx : g_cbt;
        int run = 0;
        for (int c = 0; c < nchunk; c++) { cb[c * KC + k] = run; run += cc[c * KC + k]; }
        if (t < 16) g_cntx[k] = run; else g_cntt[k] = run;
    }
    __syncthreads();
    if (t == 0) {
        int run = 0;
        for (int k = 0; k < KC; k++) {
            int m = min(g_cntx[k], g_cntt[k]);
            g_m[k] = m;
            int p = 1;
            while (p < m) p <<= 1;
            if (m == 0) p = 0;
            g_pow[k] = p;
            g_off[k] = run;
            run += p;
        }
    }
}

// ---------------- pad fill (only needed when fallback sort will run) ----------------
__global__ void fillK() {
    int mx = 0;
    #pragma unroll
    for (int k = 0; k < KC; k++) mx = max(mx, g_m[k]);
    if (mx <= 49152) return;   // all segments handled by in-register tiers
    size_t n = (size_t)2 * NMAX * DC / 4;
    float4 v = make_float4(FLT_MAX, FLT_MAX, FLT_MAX, FLT_MAX);
    for (size_t i = (size_t)blockIdx.x * blockDim.x + threadIdx.x; i < n;
         i += (size_t)gridDim.x * blockDim.x) {
        ((float4*)g_bufx)[i] = v;
        ((float4*)g_buft)[i] = v;
    }
}

// ---------------- stable scatter into per-(cluster,dim) segments ----------------
__global__ void scatterK(const float* __restrict__ src, const int* __restrict__ predIn,
                         int isx, int N) {
    __shared__ int wcnt[8][KC];
    int tid = threadIdx.x;
    if (tid < 8 * KC) ((int*)wcnt)[tid] = 0;
    __syncthreads();
    const int* pred = isx ? g_pred : predIn;
    int i = blockIdx.x * blockDim.x + tid;
    int lane = tid & 31, w = tid >> 5;
    int k = 0, lr = 0;
    bool act = i < N;
    unsigned ball = __ballot_sync(0xffffffffu, act);
    if (act) {
        k = pred[i];
        unsigned mm = __match_any_sync(ball, k);
        lr = __popc(mm & ((1u << lane) - 1u));
        if (lane == (int)(__ffs(mm) - 1)) wcnt[w][k] = __popc(mm);
    }
    __syncthreads();
    if (act) {
        int base = isx ? g_cbx[blockIdx.x * KC + k] : g_cbt[blockIdx.x * KC + k];
        #pragma unroll
        for (int ww = 0; ww < 8; ww++)
            if (ww < w) base += wcnt[ww][k];
        int r = base + lr;
        int m = g_m[k];
        if (r < m) {
            int P = g_pow[k];
            float* buf = (isx ? g_bufx : g_buft) + g_off[k] * DC + r;
            const float4* s4 = (const float4*)(src + (size_t)i * DC);
            #pragma unroll
            for (int q = 0; q < DC / 4; q++) {
                float4 v = s4[q];
                buf[(4 * q + 0) * P] = v.x;
                buf[(4 * q + 1) * P] = v.y;
                buf[(4 * q + 2) * P] = v.z;
                buf[(4 * q + 3) * P] = v.w;
            }
        }
    }
}

// ---------------- tiered per-segment radix sorts ----------------
template <int BT, int IPT, int LO>
__global__ void __launch_bounds__(BT) sortTier() {
    constexpr int CAP = BT * IPT;
    int seg = blockIdx.x;
    int k = seg >> 6, d = seg & 63;
    int m = g_m[k];
    if (m <= LO || m > CAP) return;
    float* buf = (blockIdx.y ? g_buft : g_bufx) + g_off[k] * DC + d * g_pow[k];
    typedef cub::BlockRadixSort<float, BT, IPT> BRS;
    extern __shared__ __align__(16) unsigned char smraw[];
    typename BRS::TempStorage& ts = *reinterpret_cast<typename BRS::TempStorage*>(smraw);
    float items[IPT];
    int base = threadIdx.x * IPT;
    #pragma unroll
    for (int j = 0; j < IPT; j++) {
        int idx = base + j;
        items[j] = (idx < m) ? buf[idx] : FLT_MAX;
    }
    BRS(ts).Sort(items);
    #pragma unroll
    for (int j = 0; j < IPT; j++) {
        int idx = base + j;
        if (idx < m) buf[idx] = items[j];
    }
}

// ---------------- fallback: single-block global bitonic for huge segments ----------------
__global__ void fallbackK() {
    int seg = blockIdx.x;
    int k = seg >> 6, d = seg & 63;
    int m = g_m[k];
    if (m <= 49152) return;
    int P = g_pow[k];
    float* p = (blockIdx.y ? g_buft : g_bufx) + g_off[k] * DC + d * P;
    for (int size = 2; size <= P; size <<= 1) {
        for (int stride = size >> 1; stride; stride >>= 1) {
            for (int t = threadIdx.x; t < (P >> 1); t += blockDim.x) {
                int low = t & (stride - 1);
                int i = ((t - low) << 1) + low;
                int j = i + stride;
                float a = p[i], b = p[j];
                bool up = ((i & size) == 0);
                if ((a > b) == up) { p[i] = b; p[j] = a; }
            }
            __syncthreads();
        }
    }
}

// ---------------- Wasserstein diff accumulation ----------------
__global__ void diffK() {
    int seg = blockIdx.x;
    int k = seg >> 6, d = seg & 63;
    int m = g_m[k];
    if (m <= 0) return;
    int P = g_pow[k];
    int base = g_off[k] * DC + d * P;
    float s = 0.f;
    for (int i = threadIdx.x; i < m; i += blockDim.x)
        s += fabsf(g_bufx[base + i] - g_buft[base + i]);
    __shared__ float red[256];
    red[threadIdx.x] = s;
    __syncthreads();
    for (int o = 128; o; o >>= 1) {
        if (threadIdx.x < o) red[threadIdx.x] += red[threadIdx.x + o];
        __syncthreads();
    }
    if (threadIdx.x == 0) atomicAdd(&g_loss, red[0] / ((float)m * (float)DC));
}

// ---------------- finalize ----------------
__global__ void finalK(const float* __restrict__ ft, float* __restrict__ out, int N) {
    if (threadIdx.x == 0) {
        float lf = 0.f;
        for (int k = 0; k < KC; k++) {
            float df = g_fill[k] / (float)N - ft[k];
            lf += df * df;
        }
        out[0] = g_loss + lf / (float)KC;
    }
}

extern "C" void kernel_launch(void* const* d_in, const int* in_sizes, int n_in,
                              void* d_out, int out_size) {
    const float* x  = (const float*)d_in[0];
    const float* C  = (const float*)d_in[1];
    const float* ft = (const float*)d_in[2];
    const float* tg = (const float*)d_in[3];
    const int*   pr = (const int*)d_in[4];
    float* out = (float*)d_out;
    int N = in_sizes[0] / DC;
    int nblk = (N + CHUNK - 1) / CHUNK;

    size_t s1 = sizeof(cub::BlockRadixSort<float, 256, 8>::TempStorage);
    size_t s2 = sizeof(cub::BlockRadixSort<float, 256, 32>::TempStorage);
    size_t s3 = sizeof(cub::BlockRadixSort<float, 512, 32>::TempStorage);
    size_t s4 = sizeof(cub::BlockRadixSort<float, 512, 64>::TempStorage);
    size_t s5 = sizeof(cub::BlockRadixSort<float, 512, 96>::TempStorage);
    cudaFuncSetAttribute(sortTier<256, 8, 0>,      cudaFuncAttributeMaxDynamicSharedMemorySize, (int)s1);
    cudaFuncSetAttribute(sortTier<256, 32, 2048>,  cudaFuncAttributeMaxDynamicSharedMemorySize, (int)s2);
    cudaFuncSetAttribute(sortTier<512, 32, 8192>,  cudaFuncAttributeMaxDynamicSharedMemorySize, (int)s3);
    cudaFuncSetAttribute(sortTier<512, 64, 16384>, cudaFuncAttributeMaxDynamicSharedMemorySize, (int)s4);
    cudaFuncSetAttribute(sortTier<512, 96, 32768>, cudaFuncAttributeMaxDynamicSharedMemorySize, (int)s5);

    initK<<<1, 32>>>();
    assignK<<<nblk, 256>>>(x, C, N);
    countTK<<<nblk, 256>>>(pr, N);
    scanK<<<1, 32>>>(nblk);
    fillK<<<2048, 256>>>();
    scatterK<<<nblk, 256>>>(x, pr, 1, N);
    scatterK<<<nblk, 256>>>(tg, pr, 0, N);
    sortTier<256, 8, 0>      <<<dim3(KC * DC, 2), 256, s1>>>();
    sortTier<256, 32, 2048>  <<<dim3(KC * DC, 2), 256, s2>>>();
    sortTier<512, 32, 8192>  <<<dim3(KC * DC, 2), 512, s3>>>();
    sortTier<512, 64, 16384> <<<dim3(KC * DC, 2), 512, s4>>>();
    sortTier<512, 96, 32768> <<<dim3(KC * DC, 2), 512, s5>>>();
    fallbackK<<<dim3(KC * DC, 2), 1024>>>();
    diffK<<<KC * DC, 256>>>();
    finalK<<<1, 32>>>(ft, out, N);
}